// round 2
// baseline (speedup 1.0000x reference)
#include <cuda_runtime.h>
#include <cuda_bf16.h>
#include <math.h>

// Problem constants (fixed shapes)
#define BB 4
#define SS 2048
#define DM 1024
#define NH 16
#define HD 64
#define MROWS (BB * SS)   // 8192

// ---------------- scratch (static __device__, no allocation) ----------------
__device__ float g_q[MROWS * DM];
__device__ float g_k[MROWS * DM];
__device__ float g_v[MROWS * DM];
__device__ float g_attn[MROWS * DM];
__device__ float g_z[MROWS * DM];
__device__ float g_beta[MROWS * NH];

// ---------------- SGEMM core: C[M,N] = act(A[M,K] * B[N,K]^T) ---------------
// A row-major MxK, B row-major NxK (both K-contiguous: "NT" gemm).
// BM=BN=128, BK=16, 256 threads, 8x8 per thread.
#define BM 128
#define BN 128
#define BK 16

__device__ __forceinline__
void sgemm_body(const float* __restrict__ A, const float* __restrict__ B,
                float* __restrict__ C, int K, int N, int do_silu)
{
    __shared__ __align__(16) float As[BK][BM];
    __shared__ __align__(16) float Bs[BK][BN];

    const int tid = threadIdx.x;
    const int tx = tid & 15;        // 0..15 -> N direction
    const int ty = tid >> 4;        // 0..15 -> M direction
    const int bm0 = blockIdx.y * BM;
    const int bn0 = blockIdx.x * BN;

    const float* Ab = A + (size_t)bm0 * K;
    const float* Bb = B + (size_t)bn0 * K;

    float acc[8][8];
#pragma unroll
    for (int i = 0; i < 8; i++)
#pragma unroll
        for (int j = 0; j < 8; j++) acc[i][j] = 0.f;

    for (int k0 = 0; k0 < K; k0 += BK) {
#pragma unroll
        for (int i = 0; i < 2; i++) {
            int f = tid + i * 256;          // 0..511
            int r = f >> 2;                 // 0..127
            int cg = (f & 3) << 2;          // 0,4,8,12
            float4 av = *(const float4*)(Ab + (size_t)r * K + k0 + cg);
            As[cg + 0][r] = av.x; As[cg + 1][r] = av.y;
            As[cg + 2][r] = av.z; As[cg + 3][r] = av.w;
            float4 bv = *(const float4*)(Bb + (size_t)r * K + k0 + cg);
            Bs[cg + 0][r] = bv.x; Bs[cg + 1][r] = bv.y;
            Bs[cg + 2][r] = bv.z; Bs[cg + 3][r] = bv.w;
        }
        __syncthreads();

#pragma unroll
        for (int kk = 0; kk < BK; kk++) {
            float a[8], b[8];
            *(float4*)(a)     = *(const float4*)&As[kk][ty * 8];
            *(float4*)(a + 4) = *(const float4*)&As[kk][ty * 8 + 4];
            *(float4*)(b)     = *(const float4*)&Bs[kk][tx * 8];
            *(float4*)(b + 4) = *(const float4*)&Bs[kk][tx * 8 + 4];
#pragma unroll
            for (int i = 0; i < 8; i++)
#pragma unroll
                for (int j = 0; j < 8; j++)
                    acc[i][j] = fmaf(a[i], b[j], acc[i][j]);
        }
        __syncthreads();
    }

    // epilogue (optional SiLU), vectorized stores
#pragma unroll
    for (int i = 0; i < 8; i++) {
        int row = bm0 + ty * 8 + i;
        float out[8];
#pragma unroll
        for (int j = 0; j < 8; j++) {
            float x = acc[i][j];
            if (do_silu) x = x / (1.f + expf(-x));   // silu
            out[j] = x;
        }
        float* cp = C + (size_t)row * N + bn0 + tx * 8;
        *(float4*)(cp)     = *(float4*)(out);
        *(float4*)(cp + 4) = *(float4*)(out + 4);
    }
}

// Fused QKV: gridDim.z in {0,1,2} selects (Wq->g_q, Wk->g_k, Wv->g_v)
__global__ __launch_bounds__(256, 2)
void sgemm_qkv(const float* __restrict__ x,
               const float* __restrict__ Wq,
               const float* __restrict__ Wk,
               const float* __restrict__ Wv)
{
    const float* W;
    float* C;
    if (blockIdx.z == 0)      { W = Wq; C = g_q; }
    else if (blockIdx.z == 1) { W = Wk; C = g_k; }
    else                      { W = Wv; C = g_v; }
    sgemm_body(x, W, C, DM, DM, 1);
}

// Output projection: g_z @ Wo^T -> out (no activation)
__global__ __launch_bounds__(256, 2)
void sgemm_o(const float* __restrict__ Wo, float* __restrict__ outp)
{
    sgemm_body(g_z, Wo, outp, DM, DM, 0);
}

// ---------------- beta: sigmoid(x @ Wbeta^T), (8192,16) ---------------------
__global__ __launch_bounds__(512)
void beta_kernel(const float* __restrict__ x, const float* __restrict__ Wb)
{
    __shared__ __align__(16) float sx[DM];
    const int row = blockIdx.x;
    const int tid = threadIdx.x;
    {
        float2 t = *(const float2*)(x + (size_t)row * DM + 2 * tid);
        *(float2*)(sx + 2 * tid) = t;
    }
    __syncthreads();
    const int w = tid >> 5, l = tid & 31;   // warp w -> head w (16 warps)
    const float* wrow = Wb + (size_t)w * DM;
    float s = 0.f;
#pragma unroll
    for (int i = 0; i < 8; i++) {
        int kb = i * 128 + l * 4;
        float4 wv = *(const float4*)(wrow + kb);
        float4 xv = *(const float4*)(sx + kb);
        s += wv.x * xv.x + wv.y * xv.y + wv.z * xv.z + wv.w * xv.w;
    }
#pragma unroll
    for (int o = 16; o; o >>= 1) s += __shfl_xor_sync(0xffffffffu, s, o);
    if (l == 0) g_beta[(size_t)row * NH + w] = 1.f / (1.f + expf(-s));
}

// ---------------- l2 normalize q,k per (row, head) --------------------------
__global__ __launch_bounds__(512)
void l2norm_kernel()
{
    float* arr = blockIdx.y ? g_k : g_q;
    const int row = blockIdx.x;
    const int w = threadIdx.x >> 5, l = threadIdx.x & 31;  // warp = head
    float2* p = (float2*)(arr + (size_t)row * DM + w * HD) + l;
    float2 v = *p;
    float s = v.x * v.x + v.y * v.y;
#pragma unroll
    for (int o = 16; o; o >>= 1) s += __shfl_xor_sync(0xffffffffu, s, o);
    float inv = 1.f / (sqrtf(s) + 1e-6f);
    v.x *= inv; v.y *= inv;
    *p = v;
}

// ---------------- delta-rule recurrence -------------------------------------
// One CTA per (b, head). 128 threads. M (64x64) kept twice in registers:
//  thread (col=tid>>1, half=tid&1):
//    C[i] = M[half*32+i][col]   (column copy, for out + column update)
//    R[i] = M[col][half*32+i]   (row copy, for retrieved + row update)
__global__ __launch_bounds__(128, 1)
void recurrence_kernel()
{
    const int b = blockIdx.x >> 4;
    const int n = blockIdx.x & 15;
    const int tid = threadIdx.x;
    const int col = tid >> 1;
    const int half = tid & 1;
    const int h0 = half * 32;
    const int wid = tid >> 5, lane = tid & 31;

    __shared__ __align__(16) float stage[2][200]; // [0:64)=q [64:128)=k [128:192)=v [192]=beta
    __shared__ __align__(16) float sdelta[64];

    float C[32], R[32];
#pragma unroll
    for (int i = 0; i < 32; i++) { C[i] = 0.f; R[i] = 0.f; }

    const size_t base0 = ((size_t)(b * SS) * NH + n) * HD;  // step stride = NH*HD = 1024
    const size_t bbase = (size_t)(b * SS) * NH + n;          // beta step stride = 16

    // stage s = 0
    if (wid == 0) *(float2*)&stage[0][0 + 2 * lane]   = *(const float2*)(g_q + base0 + 2 * lane);
    else if (wid == 1) *(float2*)&stage[0][64 + 2 * lane]  = *(const float2*)(g_k + base0 + 2 * lane);
    else if (wid == 2) *(float2*)&stage[0][128 + 2 * lane] = *(const float2*)(g_v + base0 + 2 * lane);
    else if (lane == 0) stage[0][192] = g_beta[bbase];
    __syncthreads();

    for (int s = 0; s < SS; s++) {
        const int p = s & 1;
        // prefetch s+1 into registers
        float2 pre = make_float2(0.f, 0.f);
        float preb = 0.f;
        const bool has = (s + 1 < SS);
        if (has) {
            size_t bn2 = base0 + (size_t)(s + 1) * (NH * HD);
            if (wid == 0) pre = *(const float2*)(g_q + bn2 + 2 * lane);
            else if (wid == 1) pre = *(const float2*)(g_k + bn2 + 2 * lane);
            else if (wid == 2) pre = *(const float2*)(g_v + bn2 + 2 * lane);
            else if (lane == 0) preb = g_beta[bbase + (size_t)(s + 1) * NH];
        }

        // phase 1: retrieved[col] = sum_d M[col][d] * k[d]
        float partial = 0.f;
#pragma unroll
        for (int j = 0; j < 8; j++) {
            float4 kv = *(const float4*)&stage[p][64 + h0 + 4 * j];
            partial = fmaf(R[4*j],   kv.x, partial);
            partial = fmaf(R[4*j+1], kv.y, partial);
            partial = fmaf(R[4*j+2], kv.z, partial);
            partial = fmaf(R[4*j+3], kv.w, partial);
        }
        partial += __shfl_xor_sync(0xffffffffu, partial, 1);
        const float bs = stage[p][192];
        const float delta = stage[p][128 + col] - partial;   // v[col] - retrieved[col]
        if (half == 0) sdelta[col] = delta;
        __syncthreads();

        // phase 2: out[col] = sum_h q[h]*M[h][col]; M[h][col] += bs*k[h]*delta[col]
        const float bd = bs * delta;
        float acc = 0.f;
#pragma unroll
        for (int j = 0; j < 8; j++) {
            float4 qv = *(const float4*)&stage[p][h0 + 4 * j];
            float4 kv = *(const float4*)&stage[p][64 + h0 + 4 * j];
            acc = fmaf(qv.x, C[4*j],   acc);
            acc = fmaf(qv.y, C[4*j+1], acc);
            acc = fmaf(qv.z, C[4*j+2], acc);
            acc = fmaf(qv.w, C[4*j+3], acc);
            C[4*j]   = fmaf(kv.x, bd, C[4*j]);
            C[4*j+1] = fmaf(kv.y, bd, C[4*j+1]);
            C[4*j+2] = fmaf(kv.z, bd, C[4*j+2]);
            C[4*j+3] = fmaf(kv.w, bd, C[4*j+3]);
        }
        // row update: M[col][d] += bs*k[col]*delta[d]
        const float bk = bs * stage[p][64 + col];
#pragma unroll
        for (int j = 0; j < 8; j++) {
            float4 dv = *(const float4*)&sdelta[h0 + 4 * j];
            R[4*j]   = fmaf(bk, dv.x, R[4*j]);
            R[4*j+1] = fmaf(bk, dv.y, R[4*j+1]);
            R[4*j+2] = fmaf(bk, dv.z, R[4*j+2]);
            R[4*j+3] = fmaf(bk, dv.w, R[4*j+3]);
        }
        acc += __shfl_xor_sync(0xffffffffu, acc, 1);
        if (half == 0) g_attn[base0 + (size_t)s * (NH * HD) + col] = acc;

        // stash prefetch into the other buffer
        if (has) {
            if (wid == 0) *(float2*)&stage[p ^ 1][0 + 2 * lane]   = pre;
            else if (wid == 1) *(float2*)&stage[p ^ 1][64 + 2 * lane]  = pre;
            else if (wid == 2) *(float2*)&stage[p ^ 1][128 + 2 * lane] = pre;
            else if (lane == 0) stage[p ^ 1][192] = preb;
        }
        __syncthreads();
    }
}

// ---------------- RMSNorm rows ----------------------------------------------
__global__ __launch_bounds__(256)
void rmsnorm_kernel(const float* __restrict__ w)
{
    __shared__ float red[8];
    const int row = blockIdx.x;
    const int tid = threadIdx.x;
    const int l = tid & 31, wd = tid >> 5;
    float4 x = ((const float4*)(g_attn + (size_t)row * DM))[tid];
    float s = x.x * x.x + x.y * x.y + x.z * x.z + x.w * x.w;
#pragma unroll
    for (int o = 16; o; o >>= 1) s += __shfl_xor_sync(0xffffffffu, s, o);
    if (l == 0) red[wd] = s;
    __syncthreads();
    if (tid < 32) {
        float t = (l < 8) ? red[l] : 0.f;
#pragma unroll
        for (int o = 4; o; o >>= 1) t += __shfl_xor_sync(0xffffffffu, t, o);
        if (l == 0) red[0] = t;
    }
    __syncthreads();
    const float total = red[0];
    const float inv = rsqrtf(total * (1.f / DM) + 1e-6f);
    float4 wv = ((const float4*)w)[tid];
    x.x *= inv * wv.x; x.y *= inv * wv.y; x.z *= inv * wv.z; x.w *= inv * wv.w;
    ((float4*)(g_z + (size_t)row * DM))[tid] = x;
}

// ---------------- launch (pure kernel launches, no runtime API) -------------
extern "C" void kernel_launch(void* const* d_in, const int* in_sizes, int n_in,
                              void* d_out, int out_size)
{
    const float* x    = (const float*)d_in[0];
    const float* Wq   = (const float*)d_in[1];
    const float* Wk   = (const float*)d_in[2];
    const float* Wv   = (const float*)d_in[3];
    const float* Wo   = (const float*)d_in[4];
    const float* Wb   = (const float*)d_in[5];
    const float* rmsw = (const float*)d_in[6];
    float* outp = (float*)d_out;

    dim3 qkv_grid(DM / BN, MROWS / BM, 3);   // (8, 64, 3)
    dim3 o_grid(DM / BN, MROWS / BM);        // (8, 64)
    dim3 gblk(256);

    // projections with fused SiLU (Q, K, V in one launch)
    sgemm_qkv<<<qkv_grid, gblk>>>(x, Wq, Wk, Wv);
    beta_kernel<<<MROWS, 512>>>(x, Wb);
    // l2 normalize q and k per head
    l2norm_kernel<<<dim3(MROWS, 2), 512>>>();
    // sequential delta-rule recurrence (64 independent states)
    recurrence_kernel<<<BB * NH, 128>>>();
    // RMSNorm + output projection
    rmsnorm_kernel<<<MROWS, 256>>>(rmsw);
    sgemm_o<<<o_grid, gblk>>>(Wo, outp);
}

// round 3
// speedup vs baseline: 1.2347x; 1.2347x over previous
#include <cuda_runtime.h>
#include <cuda_bf16.h>
#include <math.h>
#include <stdint.h>

// Problem constants (fixed shapes)
#define BB 4
#define SS 2048
#define DM 1024
#define NH 16
#define HD 64
#define MROWS (BB * SS)   // 8192

// ---------------- scratch (static __device__, no allocation) ----------------
__device__ float g_q[MROWS * DM];
__device__ float g_k[MROWS * DM];
__device__ float g_v[MROWS * DM];
__device__ float g_attn[MROWS * DM];
__device__ float g_z[MROWS * DM];
__device__ float g_beta[MROWS * NH];

// ---------------- tensor-core GEMM: C = act(A[M,K] @ B[N,K]^T) --------------
// mma.sync.m16n8k8 tf32 with 3xTF32 split (hi*hi + hi*lo + lo*hi) for fp32-
// grade accuracy. BM=BN=128, BK=32, 256 threads (8 warps: 4 in M x 2 in N).
// Each warp: 32(M) x 64(N) = 2 m16-tiles x 8 n8-tiles.

#define GBK 32
#define SPAD 36   // 32 + 4 pad: frag LDS addresses hit 32 distinct banks

__device__ __forceinline__ void mma_tf32(float* c, const uint32_t* a,
                                         uint32_t b0, uint32_t b1)
{
    asm volatile(
        "mma.sync.aligned.m16n8k8.row.col.f32.tf32.tf32.f32 "
        "{%0,%1,%2,%3},{%4,%5,%6,%7},{%8,%9},{%0,%1,%2,%3};"
        : "+f"(c[0]), "+f"(c[1]), "+f"(c[2]), "+f"(c[3])
        : "r"(a[0]), "r"(a[1]), "r"(a[2]), "r"(a[3]), "r"(b0), "r"(b1));
}

__device__ __forceinline__ void split_tf32(float x, uint32_t& hi, uint32_t& lo)
{
    asm("cvt.rna.tf32.f32 %0, %1;" : "=r"(hi) : "f"(x));
    float lf = x - __uint_as_float(hi);
    asm("cvt.rna.tf32.f32 %0, %1;" : "=r"(lo) : "f"(lf));
}

__device__ __forceinline__
void mma_gemm_body(const float* __restrict__ A, const float* __restrict__ B,
                   float* __restrict__ C, int do_silu)
{
    const int K = DM, N = DM;
    __shared__ __align__(16) float As[128][SPAD];
    __shared__ __align__(16) float Bs[128][SPAD];

    const int tid = threadIdx.x;
    const int lane = tid & 31;
    const int warp = tid >> 5;
    const int warp_m = warp & 3;       // 0..3 -> 32 rows each
    const int warp_n = warp >> 2;      // 0..1 -> 64 cols each
    const int g = lane >> 2;           // groupID 0..7
    const int tg = lane & 3;           // threadID_in_group 0..3

    const int bm0 = blockIdx.y * 128;
    const int bn0 = blockIdx.x * 128;

    // gmem load mapping: 4 float4 per thread per tile (1024 float4 total)
    int lrow[4], lcg[4];
#pragma unroll
    for (int i = 0; i < 4; i++) {
        int idx = i * 256 + tid;       // 0..1023
        lrow[i] = idx >> 3;            // 0..127
        lcg[i] = (idx & 7) << 2;       // 0,4,...,28
    }

    float acc[2][8][4];
#pragma unroll
    for (int mt = 0; mt < 2; mt++)
#pragma unroll
        for (int nt = 0; nt < 8; nt++)
#pragma unroll
            for (int r = 0; r < 4; r++) acc[mt][nt][r] = 0.f;

    // preload tile 0 into regs
    float4 pa[4], pb[4];
#pragma unroll
    for (int i = 0; i < 4; i++) {
        pa[i] = *(const float4*)(A + (size_t)(bm0 + lrow[i]) * K + lcg[i]);
        pb[i] = *(const float4*)(B + (size_t)(bn0 + lrow[i]) * K + lcg[i]);
    }

    for (int k0 = 0; k0 < K; k0 += GBK) {
        // commit prefetched tile to smem
#pragma unroll
        for (int i = 0; i < 4; i++) {
            *(float4*)&As[lrow[i]][lcg[i]] = pa[i];
            *(float4*)&Bs[lrow[i]][lcg[i]] = pb[i];
        }
        __syncthreads();

        // prefetch next tile
        if (k0 + GBK < K) {
#pragma unroll
            for (int i = 0; i < 4; i++) {
                pa[i] = *(const float4*)(A + (size_t)(bm0 + lrow[i]) * K + k0 + GBK + lcg[i]);
                pb[i] = *(const float4*)(B + (size_t)(bn0 + lrow[i]) * K + k0 + GBK + lcg[i]);
            }
        }

#pragma unroll
        for (int kk = 0; kk < GBK; kk += 8) {
            // A fragments (hi/lo) for both m16 tiles
            uint32_t ah[2][4], al[2][4];
#pragma unroll
            for (int mt = 0; mt < 2; mt++) {
                int mr = warp_m * 32 + mt * 16 + g;
                split_tf32(As[mr][kk + tg],         ah[mt][0], al[mt][0]);
                split_tf32(As[mr + 8][kk + tg],     ah[mt][1], al[mt][1]);
                split_tf32(As[mr][kk + tg + 4],     ah[mt][2], al[mt][2]);
                split_tf32(As[mr + 8][kk + tg + 4], ah[mt][3], al[mt][3]);
            }
#pragma unroll
            for (int nt = 0; nt < 8; nt++) {
                int nr = warp_n * 64 + nt * 8 + g;
                uint32_t bh0, bl0, bh1, bl1;
                split_tf32(Bs[nr][kk + tg],     bh0, bl0);
                split_tf32(Bs[nr][kk + tg + 4], bh1, bl1);
#pragma unroll
                for (int mt = 0; mt < 2; mt++) {
                    mma_tf32(acc[mt][nt], ah[mt], bh0, bh1);  // hi*hi
                    mma_tf32(acc[mt][nt], ah[mt], bl0, bl1);  // hi*lo
                    mma_tf32(acc[mt][nt], al[mt], bh0, bh1);  // lo*hi
                }
            }
        }
        __syncthreads();
    }

    // epilogue: optional SiLU, float2 stores per c-register pair
#pragma unroll
    for (int mt = 0; mt < 2; mt++) {
#pragma unroll
        for (int nt = 0; nt < 8; nt++) {
            int row0 = bm0 + warp_m * 32 + mt * 16 + g;
            int cb = bn0 + warp_n * 64 + nt * 8 + 2 * tg;
            float v0 = acc[mt][nt][0], v1 = acc[mt][nt][1];
            float v2 = acc[mt][nt][2], v3 = acc[mt][nt][3];
            if (do_silu) {
                v0 = v0 / (1.f + expf(-v0));
                v1 = v1 / (1.f + expf(-v1));
                v2 = v2 / (1.f + expf(-v2));
                v3 = v3 / (1.f + expf(-v3));
            }
            *(float2*)(C + (size_t)row0 * N + cb)       = make_float2(v0, v1);
            *(float2*)(C + (size_t)(row0 + 8) * N + cb) = make_float2(v2, v3);
        }
    }
}

// Fused QKV: blockIdx.z in {0,1,2} selects (Wq->g_q, Wk->g_k, Wv->g_v)
__global__ __launch_bounds__(256, 1)
void mma_qkv(const float* __restrict__ x,
             const float* __restrict__ Wq,
             const float* __restrict__ Wk,
             const float* __restrict__ Wv)
{
    const float* W;
    float* C;
    if (blockIdx.z == 0)      { W = Wq; C = g_q; }
    else if (blockIdx.z == 1) { W = Wk; C = g_k; }
    else                      { W = Wv; C = g_v; }
    mma_gemm_body(x, W, C, 1);
}

// Output projection: g_z @ Wo^T -> out (no activation)
__global__ __launch_bounds__(256, 1)
void mma_o(const float* __restrict__ Wo, float* __restrict__ outp)
{
    mma_gemm_body(g_z, Wo, outp, 0);
}

// ---------------- beta: sigmoid(x @ Wbeta^T), (8192,16) ---------------------
__global__ __launch_bounds__(512)
void beta_kernel(const float* __restrict__ x, const float* __restrict__ Wb)
{
    __shared__ __align__(16) float sx[DM];
    const int row = blockIdx.x;
    const int tid = threadIdx.x;
    {
        float2 t = *(const float2*)(x + (size_t)row * DM + 2 * tid);
        *(float2*)(sx + 2 * tid) = t;
    }
    __syncthreads();
    const int w = tid >> 5, l = tid & 31;   // warp w -> head w (16 warps)
    const float* wrow = Wb + (size_t)w * DM;
    float s = 0.f;
#pragma unroll
    for (int i = 0; i < 8; i++) {
        int kb = i * 128 + l * 4;
        float4 wv = *(const float4*)(wrow + kb);
        float4 xv = *(const float4*)(sx + kb);
        s += wv.x * xv.x + wv.y * xv.y + wv.z * xv.z + wv.w * xv.w;
    }
#pragma unroll
    for (int o = 16; o; o >>= 1) s += __shfl_xor_sync(0xffffffffu, s, o);
    if (l == 0) g_beta[(size_t)row * NH + w] = 1.f / (1.f + expf(-s));
}

// ---------------- l2 normalize q,k per (row, head) --------------------------
__global__ __launch_bounds__(512)
void l2norm_kernel()
{
    float* arr = blockIdx.y ? g_k : g_q;
    const int row = blockIdx.x;
    const int w = threadIdx.x >> 5, l = threadIdx.x & 31;  // warp = head
    float2* p = (float2*)(arr + (size_t)row * DM + w * HD) + l;
    float2 v = *p;
    float s = v.x * v.x + v.y * v.y;
#pragma unroll
    for (int o = 16; o; o >>= 1) s += __shfl_xor_sync(0xffffffffu, s, o);
    float inv = 1.f / (sqrtf(s) + 1e-6f);
    v.x *= inv; v.y *= inv;
    *p = v;
}

// ---------------- delta-rule recurrence -------------------------------------
// One CTA per (b, head). 128 threads. M (64x64) kept twice in registers:
//  thread (col=tid>>1, half=tid&1):
//    C[i] = M[half*32+i][col]   (column copy, for out + column update)
//    R[i] = M[col][half*32+i]   (row copy, for retrieved + row update)
__global__ __launch_bounds__(128, 1)
void recurrence_kernel()
{
    const int b = blockIdx.x >> 4;
    const int n = blockIdx.x & 15;
    const int tid = threadIdx.x;
    const int col = tid >> 1;
    const int half = tid & 1;
    const int h0 = half * 32;
    const int wid = tid >> 5, lane = tid & 31;

    __shared__ __align__(16) float stage[2][200]; // [0:64)=q [64:128)=k [128:192)=v [192]=beta
    __shared__ __align__(16) float sdelta[64];

    float C[32], R[32];
#pragma unroll
    for (int i = 0; i < 32; i++) { C[i] = 0.f; R[i] = 0.f; }

    const size_t base0 = ((size_t)(b * SS) * NH + n) * HD;  // step stride = NH*HD = 1024
    const size_t bbase = (size_t)(b * SS) * NH + n;          // beta step stride = 16

    // stage s = 0
    if (wid == 0) *(float2*)&stage[0][0 + 2 * lane]   = *(const float2*)(g_q + base0 + 2 * lane);
    else if (wid == 1) *(float2*)&stage[0][64 + 2 * lane]  = *(const float2*)(g_k + base0 + 2 * lane);
    else if (wid == 2) *(float2*)&stage[0][128 + 2 * lane] = *(const float2*)(g_v + base0 + 2 * lane);
    else if (lane == 0) stage[0][192] = g_beta[bbase];
    __syncthreads();

    for (int s = 0; s < SS; s++) {
        const int p = s & 1;
        // prefetch s+1 into registers
        float2 pre = make_float2(0.f, 0.f);
        float preb = 0.f;
        const bool has = (s + 1 < SS);
        if (has) {
            size_t bn2 = base0 + (size_t)(s + 1) * (NH * HD);
            if (wid == 0) pre = *(const float2*)(g_q + bn2 + 2 * lane);
            else if (wid == 1) pre = *(const float2*)(g_k + bn2 + 2 * lane);
            else if (wid == 2) pre = *(const float2*)(g_v + bn2 + 2 * lane);
            else if (lane == 0) preb = g_beta[bbase + (size_t)(s + 1) * NH];
        }

        // phase 1: retrieved[col] = sum_d M[col][d] * k[d]
        float partial = 0.f;
#pragma unroll
        for (int j = 0; j < 8; j++) {
            float4 kv = *(const float4*)&stage[p][64 + h0 + 4 * j];
            partial = fmaf(R[4*j],   kv.x, partial);
            partial = fmaf(R[4*j+1], kv.y, partial);
            partial = fmaf(R[4*j+2], kv.z, partial);
            partial = fmaf(R[4*j+3], kv.w, partial);
        }
        partial += __shfl_xor_sync(0xffffffffu, partial, 1);
        const float bs = stage[p][192];
        const float delta = stage[p][128 + col] - partial;   // v[col] - retrieved[col]
        if (half == 0) sdelta[col] = delta;
        __syncthreads();

        // phase 2: out[col] = sum_h q[h]*M[h][col]; M[h][col] += bs*k[h]*delta[col]
        const float bd = bs * delta;
        float acc = 0.f;
#pragma unroll
        for (int j = 0; j < 8; j++) {
            float4 qv = *(const float4*)&stage[p][h0 + 4 * j];
            float4 kv = *(const float4*)&stage[p][64 + h0 + 4 * j];
            acc = fmaf(qv.x, C[4*j],   acc);
            acc = fmaf(qv.y, C[4*j+1], acc);
            acc = fmaf(qv.z, C[4*j+2], acc);
            acc = fmaf(qv.w, C[4*j+3], acc);
            C[4*j]   = fmaf(kv.x, bd, C[4*j]);
            C[4*j+1] = fmaf(kv.y, bd, C[4*j+1]);
            C[4*j+2] = fmaf(kv.z, bd, C[4*j+2]);
            C[4*j+3] = fmaf(kv.w, bd, C[4*j+3]);
        }
        // row update: M[col][d] += bs*k[col]*delta[d]
        const float bk = bs * stage[p][64 + col];
#pragma unroll
        for (int j = 0; j < 8; j++) {
            float4 dv = *(const float4*)&sdelta[h0 + 4 * j];
            R[4*j]   = fmaf(bk, dv.x, R[4*j]);
            R[4*j+1] = fmaf(bk, dv.y, R[4*j+1]);
            R[4*j+2] = fmaf(bk, dv.z, R[4*j+2]);
            R[4*j+3] = fmaf(bk, dv.w, R[4*j+3]);
        }
        acc += __shfl_xor_sync(0xffffffffu, acc, 1);
        if (half == 0) g_attn[base0 + (size_t)s * (NH * HD) + col] = acc;

        // stash prefetch into the other buffer
        if (has) {
            if (wid == 0) *(float2*)&stage[p ^ 1][0 + 2 * lane]   = pre;
            else if (wid == 1) *(float2*)&stage[p ^ 1][64 + 2 * lane]  = pre;
            else if (wid == 2) *(float2*)&stage[p ^ 1][128 + 2 * lane] = pre;
            else if (lane == 0) stage[p ^ 1][192] = preb;
        }
        __syncthreads();
    }
}

// ---------------- RMSNorm rows ----------------------------------------------
__global__ __launch_bounds__(256)
void rmsnorm_kernel(const float* __restrict__ w)
{
    __shared__ float red[8];
    const int row = blockIdx.x;
    const int tid = threadIdx.x;
    const int l = tid & 31, wd = tid >> 5;
    float4 x = ((const float4*)(g_attn + (size_t)row * DM))[tid];
    float s = x.x * x.x + x.y * x.y + x.z * x.z + x.w * x.w;
#pragma unroll
    for (int o = 16; o; o >>= 1) s += __shfl_xor_sync(0xffffffffu, s, o);
    if (l == 0) red[wd] = s;
    __syncthreads();
    if (tid < 32) {
        float t = (l < 8) ? red[l] : 0.f;
#pragma unroll
        for (int o = 4; o; o >>= 1) t += __shfl_xor_sync(0xffffffffu, t, o);
        if (l == 0) red[0] = t;
    }
    __syncthreads();
    const float total = red[0];
    const float inv = rsqrtf(total * (1.f / DM) + 1e-6f);
    float4 wv = ((const float4*)w)[tid];
    x.x *= inv * wv.x; x.y *= inv * wv.y; x.z *= inv * wv.z; x.w *= inv * wv.w;
    ((float4*)(g_z + (size_t)row * DM))[tid] = x;
}

// ---------------- launch (pure kernel launches, no runtime API) -------------
extern "C" void kernel_launch(void* const* d_in, const int* in_sizes, int n_in,
                              void* d_out, int out_size)
{
    const float* x    = (const float*)d_in[0];
    const float* Wq   = (const float*)d_in[1];
    const float* Wk   = (const float*)d_in[2];
    const float* Wv   = (const float*)d_in[3];
    const float* Wo   = (const float*)d_in[4];
    const float* Wb   = (const float*)d_in[5];
    const float* rmsw = (const float*)d_in[6];
    float* outp = (float*)d_out;

    dim3 qkv_grid(DM / 128, MROWS / 128, 3);   // (8, 64, 3)
    dim3 o_grid(DM / 128, MROWS / 128);        // (8, 64)
    dim3 gblk(256);

    // projections with fused SiLU (Q, K, V in one launch) -- tensor cores
    mma_qkv<<<qkv_grid, gblk>>>(x, Wq, Wk, Wv);
    beta_kernel<<<MROWS, 512>>>(x, Wb);
    // l2 normalize q and k per head
    l2norm_kernel<<<dim3(MROWS, 2), 512>>>();
    // sequential delta-rule recurrence (64 independent states)
    recurrence_kernel<<<BB * NH, 128>>>();
    // RMSNorm + output projection -- tensor cores
    rmsnorm_kernel<<<MROWS, 256>>>(rmsw);
    mma_o<<<o_grid, gblk>>>(Wo, outp);
}